// round 2
// baseline (speedup 1.0000x reference)
#include <cuda_runtime.h>
#include <math.h>
#include <limits.h>

#define SS 7
#define NPTS 49
#define CCH 256
#define TILE_MAX 441   // 21x21; math bounds footprint to <= ~20x20 at level 0

__global__ __launch_bounds__(256) void oriented_roi_align_kernel(
    const float* __restrict__ f0, const float* __restrict__ f1,
    const float* __restrict__ f2, const float* __restrict__ f3,
    const float* __restrict__ rois, const int* __restrict__ levels,
    float* __restrict__ out, int N)
{
    const int roi = blockIdx.x;          // roi = b*N + n
    const int bb  = roi / N;
    const int tid = threadIdx.x;

    __shared__ float s_w00[NPTS], s_w01[NPTS], s_w10[NPTS], s_w11[NPTS];
    __shared__ int   s_off[NPTS], s_dx[NPTS], s_dyw[NPTS];
    __shared__ int   s_bbox[4];              // xlo, ylo, xhi, yhi
    __shared__ int   s_gOff[TILE_MAX];       // tile idx -> plane offset
    __shared__ float s_tile[8][2][TILE_MAX]; // per-warp double tile

    const int lvl = __ldg(levels + roi);
    int H; float scale; const float* fbase;
    switch (lvl) {
        case 0:  H = 256; scale = 0.25f;     fbase = f0; break;
        case 1:  H = 128; scale = 0.125f;    fbase = f1; break;
        case 2:  H = 64;  scale = 0.0625f;   fbase = f2; break;
        default: H = 32;  scale = 0.03125f;  fbase = f3; break;
    }
    const int HW = H * H;
    const float* base = fbase + (size_t)bb * CCH * HW;
    float* op = out + (size_t)roi * CCH * NPTS;

    if (tid == 0) {
        s_bbox[0] = INT_MAX; s_bbox[1] = INT_MAX;
        s_bbox[2] = 0;       s_bbox[3] = 0;
    }
    __syncthreads();

    // ---- per-point tap computation (49 threads), identical math to ref ----
    int x0r = 0, x1r = 0, y0r = 0, y1r = 0;
    if (tid < NPTS) {
        const float* r = rois + (size_t)roi * 6;
        const float x = r[0], y = r[1], w = r[2], h = r[3], a = r[4], b = r[5];

        const float d1 = sqrtf(4.f * a * a + h * h);   // |v3 - v1|
        const float d2 = sqrtf(w * w + 4.f * b * b);   // |v4 - v2|
        const float eps = 1e-6f;
        float V0x, V0y, V1x, V1y, V2x, V2y;
        if (d1 > d2) {
            const float sA = d1 / (d2 + eps);
            V0x = x + a;          V0y = y + 0.5f * h;
            V1x = (x + 0.5f * w) + (sA - 1.f) * (0.5f * w);
            V1y = (y + b)        + (sA - 1.f) * b;
            V2x = x - a;          V2y = y - 0.5f * h;
        } else {
            const float sB = d2 / (d1 + eps);
            V0x = (x + a)        + (sB - 1.f) * a;
            V0y = (y + 0.5f * h) + (sB - 1.f) * (0.5f * h);
            V1x = x + 0.5f * w;   V1y = y + b;
            V2x = (x - a)        - (sB - 1.f) * a;
            V2y = (y - 0.5f * h) - (sB - 1.f) * (0.5f * h);
        }
        const float hre = sqrtf((V1x - V0x) * (V1x - V0x) + (V1y - V0y) * (V1y - V0y));
        const float wre = sqrtf((V2x - V1x) * (V2x - V1x) + (V2y - V1y) * (V2y - V1y));
        float theta = atan2f(V1y - V2y, V1x - V2x);
        const float PI2 = 1.5707963267948966f;
        theta = fminf(fmaxf(theta, -PI2), PI2);
        const float ct = cosf(theta), st = sinf(theta);

        const int   i  = tid / SS, j = tid % SS;
        const float tj = (float)j / 6.f - 0.5f;
        const float ti = (float)i / 6.f - 0.5f;
        const float gx = wre * scale * tj;
        const float gy = hre * scale * ti;
        const float rx =  gx * ct + gy * st + x * scale;
        const float ry = -gx * st + gy * ct + y * scale;

        const float Wf  = (float)H;
        const float inv = 1.f / (float)(H - 1);
        const float gxn = rx * scale * inv * 2.f - 1.f;
        const float gyn = ry * scale * inv * 2.f - 1.f;
        const float px = ((gxn + 1.f) * Wf - 1.f) * 0.5f;
        const float py = ((gyn + 1.f) * Wf - 1.f) * 0.5f;

        const float x0f = floorf(px), y0f = floorf(py);
        const float wx = px - x0f, wy = py - y0f;
        x0r = min(max((int)x0f, 0), H - 1);
        x1r = min(x0r + 1, H - 1);
        y0r = min(max((int)y0f, 0), H - 1);
        y1r = min(y0r + 1, H - 1);

        s_w00[tid] = (1.f - wx) * (1.f - wy);
        s_w01[tid] = wx * (1.f - wy);
        s_w10[tid] = (1.f - wx) * wy;
        s_w11[tid] = wx * wy;

        atomicMin(&s_bbox[0], x0r);
        atomicMin(&s_bbox[1], y0r);
        atomicMax(&s_bbox[2], x1r);
        atomicMax(&s_bbox[3], y1r);
    }
    __syncthreads();

    const int xlo = s_bbox[0], ylo = s_bbox[1];
    const int TW = s_bbox[2] - xlo + 1;
    const int TH = s_bbox[3] - ylo + 1;
    const int TS = TW * TH;
    const bool big = (TS > TILE_MAX);   // safety fallback, should never trigger

    if (tid < NPTS) {
        if (!big) {
            s_off[tid] = (y0r - ylo) * TW + (x0r - xlo);
            s_dx[tid]  = x1r - x0r;
            s_dyw[tid] = (y1r - y0r) * TW;
        } else {
            s_off[tid] = y0r * H + x0r;
            s_dx[tid]  = x1r - x0r;
            s_dyw[tid] = (y1r - y0r) * H;
        }
    }
    if (!big) {
        for (int idx = tid; idx < TS; idx += 256) {
            const int ty = idx / TW;
            s_gOff[idx] = (ylo + ty) * H + xlo + (idx - ty * TW);
        }
    }
    __syncthreads();

    const int warp = tid >> 5;
    const int lane = tid & 31;

    // Register-cache the two points this lane owns
    const int  pA = lane;
    const bool hasB = (32 + lane) < NPTS;
    const int  pB = hasB ? 32 + lane : 0;

    const float wa00 = s_w00[pA], wa01 = s_w01[pA], wa10 = s_w10[pA], wa11 = s_w11[pA];
    const int   offA = s_off[pA], dxA = s_dx[pA], dywA = s_dyw[pA];
    const float wb00 = s_w00[pB], wb01 = s_w01[pB], wb10 = s_w10[pB], wb11 = s_w11[pB];
    const int   offB = s_off[pB], dxB = s_dx[pB], dywB = s_dyw[pB];

    if (!big) {
        float* t0 = &s_tile[warp][0][0];
        float* t1 = &s_tile[warp][1][0];
        for (int t = 0; t < 32; t += 2) {
            const int c0 = warp + 8 * t;
            const float* pl0 = base + (size_t)c0 * HW;
            const float* pl1 = pl0 + (size_t)8 * HW;
            for (int idx = lane; idx < TS; idx += 32) {
                const int g = s_gOff[idx];
                t0[idx] = __ldg(pl0 + g);
                t1[idx] = __ldg(pl1 + g);
            }
            __syncwarp();
            float* o0 = op + c0 * NPTS;
            float* o1 = o0 + 8 * NPTS;
            o0[pA] = t0[offA] * wa00 + t0[offA + dxA] * wa01
                   + t0[offA + dywA] * wa10 + t0[offA + dxA + dywA] * wa11;
            o1[pA] = t1[offA] * wa00 + t1[offA + dxA] * wa01
                   + t1[offA + dywA] * wa10 + t1[offA + dxA + dywA] * wa11;
            if (hasB) {
                o0[pB] = t0[offB] * wb00 + t0[offB + dxB] * wb01
                       + t0[offB + dywB] * wb10 + t0[offB + dxB + dywB] * wb11;
                o1[pB] = t1[offB] * wb00 + t1[offB + dxB] * wb01
                       + t1[offB + dywB] * wb10 + t1[offB + dxB + dywB] * wb11;
            }
            __syncwarp();
        }
    } else {
        // fallback: direct gather with absolute offsets (never expected)
        for (int t = 0; t < 32; t++) {
            const int c = warp + 8 * t;
            const float* pl = base + (size_t)c * HW;
            float* o = op + c * NPTS;
            o[pA] = __ldg(pl + offA) * wa00 + __ldg(pl + offA + dxA) * wa01
                  + __ldg(pl + offA + dywA) * wa10 + __ldg(pl + offA + dxA + dywA) * wa11;
            if (hasB) {
                o[pB] = __ldg(pl + offB) * wb00 + __ldg(pl + offB + dxB) * wb01
                      + __ldg(pl + offB + dywB) * wb10 + __ldg(pl + offB + dxB + dywB) * wb11;
            }
        }
    }
}

extern "C" void kernel_launch(void* const* d_in, const int* in_sizes, int n_in,
                              void* d_out, int out_size) {
    const float* f0 = (const float*)d_in[0];
    const float* f1 = (const float*)d_in[1];
    const float* f2 = (const float*)d_in[2];
    const float* f3 = (const float*)d_in[3];
    const float* rois = (const float*)d_in[4];
    const int* levels = (const int*)d_in[5];
    float* out = (float*)d_out;

    const int B = in_sizes[0] / (256 * 256 * 256);
    const int total = in_sizes[5];        // B*N rois
    const int N = total / (B > 0 ? B : 1);

    oriented_roi_align_kernel<<<total, 256>>>(f0, f1, f2, f3, rois, levels, out, N);
}

// round 3
// speedup vs baseline: 1.4640x; 1.4640x over previous
#include <cuda_runtime.h>
#include <math.h>

#define SS 7
#define NPTS 49
#define CCH 256

__global__ __launch_bounds__(256) void oriented_roi_align_kernel(
    const float* __restrict__ f0, const float* __restrict__ f1,
    const float* __restrict__ f2, const float* __restrict__ f3,
    const float* __restrict__ rois, const int* __restrict__ levels,
    float* __restrict__ out, int N)
{
    const int roi = blockIdx.x;          // roi = b*N + n
    const int bb  = roi / N;
    const int tid = threadIdx.x;

    __shared__ float s_w00[NPTS], s_w01[NPTS], s_w10[NPTS], s_w11[NPTS];
    __shared__ int   s_o00[NPTS], s_o01[NPTS], s_o10[NPTS], s_o11[NPTS];

    const int lvl = __ldg(levels + roi);
    int H; float scale; const float* fbase;
    switch (lvl) {
        case 0:  H = 256; scale = 0.25f;     fbase = f0; break;
        case 1:  H = 128; scale = 0.125f;    fbase = f1; break;
        case 2:  H = 64;  scale = 0.0625f;   fbase = f2; break;
        default: H = 32;  scale = 0.03125f;  fbase = f3; break;
    }
    const int HW = H * H;
    const float* base = fbase + (size_t)bb * CCH * HW;
    float* op = out + (size_t)roi * CCH * NPTS;

    if (tid < NPTS) {
        const float* r = rois + (size_t)roi * 6;
        const float x = r[0], y = r[1], w = r[2], h = r[3], a = r[4], b = r[5];

        // ---- parallelogram -> rectangle (matches reference) ----
        const float d1 = sqrtf(4.f * a * a + h * h);   // |v3 - v1|
        const float d2 = sqrtf(w * w + 4.f * b * b);   // |v4 - v2|
        const float eps = 1e-6f;
        float V0x, V0y, V1x, V1y, V2x, V2y;
        if (d1 > d2) {
            const float sA = d1 / (d2 + eps);
            V0x = x + a;          V0y = y + 0.5f * h;
            V1x = (x + 0.5f * w) + (sA - 1.f) * (0.5f * w);
            V1y = (y + b)        + (sA - 1.f) * b;
            V2x = x - a;          V2y = y - 0.5f * h;
        } else {
            const float sB = d2 / (d1 + eps);
            V0x = (x + a)        + (sB - 1.f) * a;
            V0y = (y + 0.5f * h) + (sB - 1.f) * (0.5f * h);
            V1x = x + 0.5f * w;   V1y = y + b;
            V2x = (x - a)        - (sB - 1.f) * a;
            V2y = (y - 0.5f * h) - (sB - 1.f) * (0.5f * h);
        }
        const float hre = sqrtf((V1x - V0x) * (V1x - V0x) + (V1y - V0y) * (V1y - V0y));
        const float wre = sqrtf((V2x - V1x) * (V2x - V1x) + (V2y - V1y) * (V2y - V1y));
        float theta = atan2f(V1y - V2y, V1x - V2x);
        const float PI2 = 1.5707963267948966f;
        theta = fminf(fmaxf(theta, -PI2), PI2);
        const float ct = cosf(theta), st = sinf(theta);

        // ---- sample point for this (i, j) ----
        const int   i  = tid / SS, j = tid % SS;
        const float tj = (float)j / 6.f - 0.5f;
        const float ti = (float)i / 6.f - 0.5f;
        const float gx = wre * scale * tj;
        const float gy = hre * scale * ti;
        const float rx =  gx * ct + gy * st + x * scale;
        const float ry = -gx * st + gy * ct + y * scale;

        const float Wf  = (float)H;
        const float inv = 1.f / (float)(H - 1);
        const float gxn = rx * scale * inv * 2.f - 1.f;
        const float gyn = ry * scale * inv * 2.f - 1.f;
        const float px = ((gxn + 1.f) * Wf - 1.f) * 0.5f;
        const float py = ((gyn + 1.f) * Wf - 1.f) * 0.5f;

        const float x0f = floorf(px), y0f = floorf(py);
        const float wx = px - x0f, wy = py - y0f;
        const int x0 = min(max((int)x0f, 0), H - 1);
        const int x1 = min(x0 + 1, H - 1);
        const int y0 = min(max((int)y0f, 0), H - 1);
        const int y1 = min(y0 + 1, H - 1);

        s_o00[tid] = y0 * H + x0;
        s_o01[tid] = y0 * H + x1;
        s_o10[tid] = y1 * H + x0;
        s_o11[tid] = y1 * H + x1;
        s_w00[tid] = (1.f - wx) * (1.f - wy);
        s_w01[tid] = wx * (1.f - wy);
        s_w10[tid] = (1.f - wx) * wy;
        s_w11[tid] = wx * wy;
    }
    __syncthreads();

    const int warp = tid >> 5;
    const int lane = tid & 31;

    // Register-cache the (up to) two points this lane owns.
    const int  pA = lane;
    const bool hasB = (32 + lane) < NPTS;
    const int  pB = hasB ? 32 + lane : 0;

    const int   a00 = s_o00[pA], a01 = s_o01[pA], a10 = s_o10[pA], a11 = s_o11[pA];
    const float wa00 = s_w00[pA], wa01 = s_w01[pA], wa10 = s_w10[pA], wa11 = s_w11[pA];
    const int   b00 = s_o00[pB], b01 = s_o01[pB], b10 = s_o10[pB], b11 = s_o11[pB];
    const float wb00 = s_w00[pB], wb01 = s_w01[pB], wb10 = s_w10[pB], wb11 = s_w11[pB];

    // Channel loop: warp handles channels c = warp + 8k, unrolled x2 for MLP.
    #pragma unroll 1
    for (int c = warp; c < CCH; c += 16) {
        const float* pl0 = base + (size_t)c * HW;
        const float* pl1 = pl0 + (size_t)8 * HW;
        float* o0 = op + c * NPTS;
        float* o1 = o0 + 8 * NPTS;

        // issue all independent loads first
        const float v0a00 = __ldg(pl0 + a00), v0a01 = __ldg(pl0 + a01);
        const float v0a10 = __ldg(pl0 + a10), v0a11 = __ldg(pl0 + a11);
        const float v1a00 = __ldg(pl1 + a00), v1a01 = __ldg(pl1 + a01);
        const float v1a10 = __ldg(pl1 + a10), v1a11 = __ldg(pl1 + a11);

        float v0b00 = 0.f, v0b01 = 0.f, v0b10 = 0.f, v0b11 = 0.f;
        float v1b00 = 0.f, v1b01 = 0.f, v1b10 = 0.f, v1b11 = 0.f;
        if (hasB) {
            v0b00 = __ldg(pl0 + b00); v0b01 = __ldg(pl0 + b01);
            v0b10 = __ldg(pl0 + b10); v0b11 = __ldg(pl0 + b11);
            v1b00 = __ldg(pl1 + b00); v1b01 = __ldg(pl1 + b01);
            v1b10 = __ldg(pl1 + b10); v1b11 = __ldg(pl1 + b11);
        }

        o0[pA] = v0a00 * wa00 + v0a01 * wa01 + v0a10 * wa10 + v0a11 * wa11;
        o1[pA] = v1a00 * wa00 + v1a01 * wa01 + v1a10 * wa10 + v1a11 * wa11;
        if (hasB) {
            o0[pB] = v0b00 * wb00 + v0b01 * wb01 + v0b10 * wb10 + v0b11 * wb11;
            o1[pB] = v1b00 * wb00 + v1b01 * wb01 + v1b10 * wb10 + v1b11 * wb11;
        }
    }
}

extern "C" void kernel_launch(void* const* d_in, const int* in_sizes, int n_in,
                              void* d_out, int out_size) {
    const float* f0 = (const float*)d_in[0];
    const float* f1 = (const float*)d_in[1];
    const float* f2 = (const float*)d_in[2];
    const float* f3 = (const float*)d_in[3];
    const float* rois = (const float*)d_in[4];
    const int* levels = (const int*)d_in[5];
    float* out = (float*)d_out;

    const int B = in_sizes[0] / (256 * 256 * 256);
    const int total = in_sizes[5];        // B*N rois
    const int N = total / (B > 0 ? B : 1);

    oriented_roi_align_kernel<<<total, 256>>>(f0, f1, f2, f3, rois, levels, out, N);
}